// round 17
// baseline (speedup 1.0000x reference)
#include <cuda_runtime.h>
#include <math.h>

#define HH 512
#define WW 1024
#define BATCH 4
#define BW 16
#define TH 16
#define TY 8    // thread rows; each thread owns pixel rows 2*ty and 2*ty+1

typedef unsigned long long ull;

// ---------------- packed f32x2 primitives (sm_103a) ----------------
__device__ __forceinline__ ull pack2(float lo, float hi) {
    ull v;
    asm("mov.b64 %0, {%1, %2};" : "=l"(v)
        : "r"(__float_as_uint(lo)), "r"(__float_as_uint(hi)));
    return v;
}
__device__ __forceinline__ void unpack2(ull v, float& lo, float& hi) {
    unsigned a, b;
    asm("mov.b64 {%0, %1}, %2;" : "=r"(a), "=r"(b) : "l"(v));
    lo = __uint_as_float(a);
    hi = __uint_as_float(b);
}
__device__ __forceinline__ ull add2(ull a, ull b) {
    ull d; asm("add.rn.f32x2 %0, %1, %2;" : "=l"(d) : "l"(a), "l"(b)); return d;
}
__device__ __forceinline__ ull sub2(ull a, ull b) {
    ull d; asm("sub.rn.f32x2 %0, %1, %2;" : "=l"(d) : "l"(a), "l"(b)); return d;
}
__device__ __forceinline__ ull mul2(ull a, ull b) {
    ull d; asm("mul.rn.f32x2 %0, %1, %2;" : "=l"(d) : "l"(a), "l"(b)); return d;
}
__device__ __forceinline__ ull fma2(ull a, ull b, ull c) {
    ull d; asm("fma.rn.f32x2 %0, %1, %2, %3;" : "=l"(d) : "l"(a), "l"(b), "l"(c)); return d;
}
__device__ __forceinline__ ull neg2(ull a) { return a ^ 0x8000000080000000ULL; }

// ---------------- ray tables (sin/cos in double, rounded to fp32) ----------
__device__ float g_st[WW];
__device__ float g_ct[WW];
__device__ float g_sp[HH];
__device__ float g_cp[HH];

// sin and cos split across threads; same double expressions -> identical tables.
__global__ void rays_kernel() {
    int t = blockIdx.x * blockDim.x + threadIdx.x;
    const float PI_F = 3.14159265358979323846f;   // fl32(pi)
    if (t < 2 * WW) {
        int j = (t >= WW) ? t - WW : t;
        float jn = __fmul_rn((float)j + 0.5f, 1.0f / (float)WW);
        float th = __fsub_rn(__fmul_rn(jn, __fmul_rn(2.0f, PI_F)), PI_F);
        double thd = (double)th;
        if (t < WW) g_st[j] = (float)sin(thd);
        else        g_ct[j] = (float)cos(thd);
    } else if (t < 2 * WW + 2 * HH) {
        int u = t - 2 * WW;
        int i = (u >= HH) ? u - HH : u;
        float in_ = __fmul_rn((float)i + 0.5f, 1.0f / (float)HH);
        float ph = __fsub_rn(0.5f * PI_F, __fmul_rn(in_, PI_F));
        double phd = (double)ph;
        if (u < HH) g_sp[i] = (float)sin(phd);
        else        g_cp[i] = (float)cos(phd);
    }
}

// packed Kahan-compensated 2x2 determinant (per-lane identical to scalar det2)
__device__ __forceinline__ ull det2_2(ull a, ull b, ull c, ull d) {
    ull p = mul2(a, b);
    ull e = fma2(a, b, neg2(p));
    ull q = mul2(c, d);
    ull f = fma2(c, d, neg2(q));
    return add2(sub2(p, q), sub2(e, f));
}
// packed compensated a*x + b*y + c*z (per-lane identical to scalar dot3c)
__device__ __forceinline__ ull dot3c_2(ull a, ull x, ull b, ull y,
                                       ull c, ull z) {
    ull p0 = mul2(a, x), e0 = fma2(a, x, neg2(p0));
    ull p1 = mul2(b, y), e1 = fma2(b, y, neg2(p1));
    ull p2 = mul2(c, z), e2 = fma2(c, z, neg2(p2));
    ull s  = add2(p0, p1);
    ull t  = sub2(s, p0);
    ull er1 = add2(sub2(p0, sub2(s, t)), sub2(p1, t));
    ull s2 = add2(s, p2);
    ull t2 = sub2(s2, s);
    ull er2 = add2(sub2(s, sub2(s2, t2)), sub2(p2, t2));
    ull lo = add2(add2(er1, er2), add2(add2(e0, e1), e2));
    return add2(s2, lo);
}

__global__ __launch_bounds__(BW * TY, 12)
void normals_kernel(const float* __restrict__ depth, float* __restrict__ out) {
    __shared__ float4 pts[TH + 2][BW + 2];  // rotated-frame points
    __shared__ float4 H1[TH + 2][BW];       // xx, xy, xz, yy
    __shared__ float4 H2[TH + 2][BW];       // yz, zz, bx, by
    __shared__ float  H3[TH + 2][BW];       // bz

    const int bb = blockIdx.z;
    const int i0 = blockIdx.y * TH;
    const int j0 = blockIdx.x * BW;
    const int tid = threadIdx.y * BW + threadIdx.x;
    const int NT = BW * TY;   // 128
    const float* dptr = depth + (size_t)bb * (HH * WW);

    // Per-block basis from the center pixel's ray.
    const int ic = i0 + TH / 2;
    const int jc = j0 + BW / 2;
    float r1x = g_cp[ic] * g_st[jc];
    float r1y = g_sp[ic];
    float r1z = g_cp[ic] * g_ct[jc];
    float ax, ay, az;
    if (fabsf(r1y) < 0.9f) { ax = 0.f; ay = 1.f; az = 0.f; }
    else                   { ax = 1.f; ay = 0.f; az = 0.f; }
    float b2x = r1y * az - r1z * ay;
    float b2y = r1z * ax - r1x * az;
    float b2z = r1x * ay - r1y * ax;
    float inv2 = rsqrtf(b2x * b2x + b2y * b2y + b2z * b2z);
    b2x *= inv2; b2y *= inv2; b2z *= inv2;
    float b3x = r1y * b2z - r1z * b2y;
    float b3y = r1z * b2x - r1x * b2z;
    float b3z = r1x * b2y - r1y * b2x;

    // Phase A: rotated fp32 point tile, zero-padded.
#pragma unroll
    for (int t = tid; t < (TH + 2) * (BW + 2); t += NT) {
        int ly = t / (BW + 2);
        int lx = t - ly * (BW + 2);
        int gi = i0 + ly - 1;
        int gj = j0 + lx - 1;
        float4 q = make_float4(0.f, 0.f, 0.f, 0.f);
        if (gi >= 0 && gi < HH && gj >= 0 && gj < WW) {
            float d  = __ldg(&dptr[(size_t)gi * WW + gj]);
            float st = g_st[gj];
            float ct = g_ct[gj];
            float sp = g_sp[gi];
            float cp = g_cp[gi];
            float px = __fmul_rn(d, __fmul_rn(cp, st));
            float py = __fmul_rn(d, sp);
            float pz = __fmul_rn(d, __fmul_rn(cp, ct));
            q.x = fmaf(r1x, px, fmaf(r1y, py, r1z * pz));
            q.y = fmaf(b2x, px, fmaf(b2y, py, b2z * pz));
            q.z = fmaf(b3x, px, fmaf(b3y, py, b3z * pz));
        }
        pts[ly][lx] = q;
    }
    __syncthreads();

    // Phase B: horizontal 3-window sums, plain fp32.
#pragma unroll
    for (int t = tid; t < (TH + 2) * BW; t += NT) {
        int ly = t >> 4;          // /BW
        int lx = t & (BW - 1);
        float4 p0 = pts[ly][lx];
        float4 p1 = pts[ly][lx + 1];
        float4 p2 = pts[ly][lx + 2];
        float xx = fmaf(p2.x, p2.x, fmaf(p1.x, p1.x, p0.x * p0.x));
        float xy = fmaf(p2.x, p2.y, fmaf(p1.x, p1.y, p0.x * p0.y));
        float xz = fmaf(p2.x, p2.z, fmaf(p1.x, p1.z, p0.x * p0.z));
        float yy = fmaf(p2.y, p2.y, fmaf(p1.y, p1.y, p0.y * p0.y));
        float yz = fmaf(p2.y, p2.z, fmaf(p1.y, p1.z, p0.y * p0.z));
        float zz = fmaf(p2.z, p2.z, fmaf(p1.z, p1.z, p0.z * p0.z));
        float sx = __fadd_rn(__fadd_rn(p0.x, p1.x), p2.x);
        float sy = __fadd_rn(__fadd_rn(p0.y, p1.y), p2.y);
        float sz = __fadd_rn(__fadd_rn(p0.z, p1.z), p2.z);
        H1[ly][lx] = make_float4(xx, xy, xz, yy);
        H2[ly][lx] = make_float4(yz, zz, sx, sy);
        H3[ly][lx] = sz;
    }
    __syncthreads();

    // Phase C: two vertically-adjacent pixels per thread, PACKED solve
    // (lane0 = pixel row 2ty, lane1 = row 2ty+1). Per-lane IEEE op sequence
    // identical to the scalar version -> bit-identical output.
    const int ty = threadIdx.y;
    const int tx = threadIdx.x;
    const int r0 = 2 * ty;

    float4 u0 = H1[r0][tx], u1 = H1[r0 + 1][tx];
    float4 u2 = H1[r0 + 2][tx], u3 = H1[r0 + 3][tx];
    float4 v0 = H2[r0][tx], v1 = H2[r0 + 1][tx];
    float4 v2 = H2[r0 + 2][tx], v3 = H2[r0 + 3][tx];
    float w0 = H3[r0][tx], w1 = H3[r0 + 1][tx];
    float w2 = H3[r0 + 2][tx], w3 = H3[r0 + 3][tx];

    // Packed vertical sums: lane0 = (h0+h1)+h2, lane1 = (h1+h2)+h3.
#define VSUM(q0, q1, q2, q3) \
    add2(add2(pack2(q0, q1), pack2(q1, q2)), pack2(q2, q3))

    ull Ga = VSUM(u0.x, u1.x, u2.x, u3.x);
    ull Gb = VSUM(u0.y, u1.y, u2.y, u3.y);
    ull Gc = VSUM(u0.z, u1.z, u2.z, u3.z);
    ull Gd = VSUM(u0.w, u1.w, u2.w, u3.w);
    ull Ge = VSUM(v0.x, v1.x, v2.x, v3.x);
    ull Gf = VSUM(v0.y, v1.y, v2.y, v3.y);
    ull Bx = VSUM(v0.z, v1.z, v2.z, v3.z);
    ull By = VSUM(v0.w, v1.w, v2.w, v3.w);
    ull Bz = VSUM(w0, w1, w2, w3);
#undef VSUM

    const ull EPS2 = pack2(1e-5f, 1e-5f);
    Ga = add2(Ga, EPS2);
    Gd = add2(Gd, EPS2);
    Gf = add2(Gf, EPS2);

    ull A00 = det2_2(Gd, Gf, Ge, Ge);
    ull A01 = det2_2(Gc, Ge, Gb, Gf);
    ull A02 = det2_2(Gb, Ge, Gc, Gd);
    ull A11 = det2_2(Ga, Gf, Gc, Gc);
    ull A12 = det2_2(Gb, Gc, Ga, Ge);
    ull A22 = det2_2(Ga, Gd, Gb, Gb);

    ull m0 = dot3c_2(A00, Bx, A01, By, A02, Bz);
    ull m1 = dot3c_2(A01, Bx, A11, By, A12, Bz);
    ull m2 = dot3c_2(A02, Bx, A12, By, A22, Bz);

    // Rotate back (basis constants broadcast to both lanes).
    ull R1X = pack2(r1x, r1x), R1Y = pack2(r1y, r1y), R1Z = pack2(r1z, r1z);
    ull B2X = pack2(b2x, b2x), B2Y = pack2(b2y, b2y), B2Z = pack2(b2z, b2z);
    ull B3X = pack2(b3x, b3x), B3Y = pack2(b3y, b3y), B3Z = pack2(b3z, b3z);

    ull nxp = fma2(m0, R1X, fma2(m1, B2X, mul2(m2, B3X)));
    ull nyp = fma2(m0, R1Y, fma2(m1, B2Y, mul2(m2, B3Y)));
    ull nzp = fma2(m0, R1Z, fma2(m1, B2Z, mul2(m2, B3Z)));

    ull nnp = fma2(nxp, nxp, fma2(nyp, nyp, mul2(nzp, nzp)));

    float nx0, nx1, ny0, ny1, nz0, nz1, nn0, nn1;
    unpack2(nxp, nx0, nx1);
    unpack2(nyp, ny0, ny1);
    unpack2(nzp, nz0, nz1);
    unpack2(nnp, nn0, nn1);

    float norm0 = sqrtf(nn0); if (norm0 == 0.0f) norm0 = 1e-4f;
    float norm1 = sqrtf(nn1); if (norm1 == 0.0f) norm1 = 1e-4f;

    const int gi = i0 + r0;
    const int gj = j0 + tx;
    size_t base = (size_t)bb * 3 * (HH * WW) + (size_t)gi * WW + gj;
    out[base]               = __fdiv_rn(-nx0, norm0);
    out[base +     HH * WW] = __fdiv_rn(-ny0, norm0);
    out[base + 2 * HH * WW] = __fdiv_rn(-nz0, norm0);
    base += WW;
    out[base]               = __fdiv_rn(-nx1, norm1);
    out[base +     HH * WW] = __fdiv_rn(-ny1, norm1);
    out[base + 2 * HH * WW] = __fdiv_rn(-nz1, norm1);
}

extern "C" void kernel_launch(void* const* d_in, const int* in_sizes, int n_in,
                              void* d_out, int out_size) {
    const float* depth = (const float*)d_in[0];
    float* out = (float*)d_out;

    rays_kernel<<<(2 * (WW + HH) + 255) / 256, 256>>>();

    dim3 block(BW, TY, 1);
    dim3 grid(WW / BW, HH / TH, BATCH);
    normals_kernel<<<grid, block>>>(depth, out);
}